// round 4
// baseline (speedup 1.0000x reference)
#include <cuda_runtime.h>
#include <math.h>

#define T_LEN 4096
#define NB 2
#define DIM 512
#define CD 14
#define CS 16384
#define NTOK (NB * T_LEN)     // 8192
#define TPB 64                // tokens per block
#define CG  8                 // channel groups
#define CPT (DIM / CG)        // 64 channels per group
#define NTHR 512
#define NBLK (NTOK / TPB)     // 128 blocks = one wave

// ---------------- scratch (zero-initialized at module load; the last block
// of every launch resets it to zero, so graph replays always start clean) ----
__device__ float  g_avg_prob[CS];
__device__ int    g_occ[CS];
__device__ double g_ent;
__device__ double g_commit;
__device__ int    g_ctr;

__global__ __launch_bounds__(NTHR) void k_fused(
    const float* __restrict__ z_e,    // (B, DIM, T)
    const float* __restrict__ W_in,   // (CD, DIM)
    const float* __restrict__ b_in,   // (CD,)
    const float* __restrict__ W_out,  // (DIM, CD)
    const float* __restrict__ b_out,  // (DIM,)
    float* __restrict__ out, int out_size)
{
    // 32KB buffer, time-multiplexed:
    //  A: W_in transposed+padded [c*16+d]                (8192 floats)
    //  B: part [g][u][d] = 8*64*14 = 7168, xs at 7232..8128
    //  C: W_out padded [c*16+d]                          (8192 floats)
    __shared__ __align__(16) float buf[8192];
    __shared__ int    s_idx[TPB];
    __shared__ int    s_last;
    __shared__ double s_red[16];
    __shared__ int    s_redc[16];

    float* Ws   = buf;
    float* part = buf;
    float* xs   = buf + 7232;

    const int tid = threadIdx.x;
    const int u = tid & 63;          // token lane
    const int g = tid >> 6;          // channel group
    const int tok0 = blockIdx.x * TPB;
    const int b = tok0 >> 12;
    const int tbase = tok0 & (T_LEN - 1);

    // ---- phase A: load W_in (transposed, padded to 16) ----
    for (int i = tid; i < DIM * 16; i += NTHR) {
        int c = i >> 4, d = i & 15;
        Ws[i] = (d < CD) ? W_in[d * DIM + c] : 0.0f;
    }
    __syncthreads();

    // ---- projection: each thread accumulates 64 channels for one token ----
    const float* zp = z_e + (size_t)b * DIM * T_LEN + tbase + u;
    float acc[CD];
#pragma unroll
    for (int d = 0; d < CD; d++) acc[d] = 0.0f;

    const int c0 = g * CPT;
#pragma unroll 4
    for (int cc = 0; cc < CPT; cc++) {
        int c = c0 + cc;
        float z = __ldg(zp + (size_t)c * T_LEN);
        const float4* w4 = reinterpret_cast<const float4*>(&Ws[c << 4]);
        float4 wa = w4[0], wb = w4[1], wc = w4[2], wd = w4[3];
        acc[0]  += z * wa.x;  acc[1]  += z * wa.y;  acc[2]  += z * wa.z;  acc[3]  += z * wa.w;
        acc[4]  += z * wb.x;  acc[5]  += z * wb.y;  acc[6]  += z * wb.z;  acc[7]  += z * wb.w;
        acc[8]  += z * wc.x;  acc[9]  += z * wc.y;  acc[10] += z * wc.z;  acc[11] += z * wc.w;
        acc[12] += z * wd.x;  acc[13] += z * wd.y;
    }
    __syncthreads();   // Ws dead; reuse as part/xs

    {
        float* pr = &part[(g * TPB + u) * CD];
#pragma unroll
        for (int d = 0; d < CD; d++) pr[d] = acc[d];
    }
    __syncthreads();

    // deterministic reduction across the 8 channel groups
    for (int i = tid; i < TPB * CD; i += NTHR) {
        float s = 0.0f;
#pragma unroll
        for (int gg = 0; gg < CG; gg++) s += part[gg * (TPB * CD) + i];
        xs[i] = s + __ldg(&b_in[i % CD]);
    }
    __syncthreads();

    // ---- pull x into registers (threads 0..63) and publish packed indices ----
    float x[CD];
    int myidx_tok = 0;
    if (tid < TPB) {
#pragma unroll
        for (int d = 0; d < CD; d++) x[d] = xs[tid * CD + d];
#pragma unroll
        for (int d = 0; d < CD; d++)
            if (x[d] > 0.0f) myidx_tok |= (1 << (13 - d));
        s_idx[tid] = myidx_tok;
    }
    __syncthreads();   // xs consumed; s_idx visible; buf free

    // ---- phase C: load W_out (padded to 16) ----
    for (int i = tid; i < DIM * 16; i += NTHR) {
        int c = i >> 4, d = i & 15;
        buf[i] = (d < CD) ? __ldg(&W_out[c * CD + d]) : 0.0f;
    }
    __syncthreads();

    // ---- z_q writeout: thread (u,g) writes token u for channels g*64..+63 ----
    {
        const unsigned nix = ~(unsigned)s_idx[u];
        float* op = out + (size_t)b * DIM * T_LEN + tbase + u;
#pragma unroll 4
        for (int cc = 0; cc < CPT; cc++) {
            int c = c0 + cc;
            const float4* w4 = reinterpret_cast<const float4*>(&buf[c << 4]);
            float4 wa = w4[0], wb = w4[1], wc = w4[2], wd = w4[3];
            float s = __ldg(&b_out[c]);
            const unsigned* wu = reinterpret_cast<const unsigned*>(&wa);
            // unrolled xor-sign adds: bit(13-d) of idx ==1 -> +w else -w
#pragma unroll
            for (int d = 0; d < 4; d++)
                s += __int_as_float(reinterpret_cast<const unsigned*>(&wa)[d] ^ ((nix << (18 + d)) & 0x80000000u));
#pragma unroll
            for (int d = 0; d < 4; d++)
                s += __int_as_float(reinterpret_cast<const unsigned*>(&wb)[d] ^ ((nix << (22 + d)) & 0x80000000u));
#pragma unroll
            for (int d = 0; d < 4; d++)
                s += __int_as_float(reinterpret_cast<const unsigned*>(&wc)[d] ^ ((nix << (26 + d)) & 0x80000000u));
#pragma unroll
            for (int d = 0; d < 2; d++)
                s += __int_as_float(reinterpret_cast<const unsigned*>(&wd)[d] ^ ((nix << (30 + d)) & 0x80000000u));
            (void)wu;
            op[(size_t)c * T_LEN] = s;
        }
    }

    // ---- per-token stats (threads 0..63), overlapping the store drain ----
    if (tid < TPB) {
        g_occ[myidx_tok] = 1;

        float cm = 0.0f;
#pragma unroll
        for (int d = 0; d < CD; d++) {
            float sgn = (x[d] > 0.0f) ? 1.0f : -1.0f;
            float df = x[d] - sgn;
            cm += df * df;
        }

        float ent = 0.0f;
        float p0 = 1.0f;
        float ev[CD];
        int bp[CD];
        int m = 0;
#pragma unroll
        for (int d = 0; d < CD; d++) {
            float t = 400.0f * fabsf(x[d]);
            float e = expf(-t);                       // q/(1-q)
            p0 *= 1.0f / (1.0f + e);
            ent += log1pf(e) + t * e / (1.0f + e);    // stable Bernoulli entropy
            if (e >= 1e-8f) { ev[m] = e; bp[m] = 1 << (13 - d); m++; }
        }

        const int nsub = 1 << m;
        for (int s = 0; s < nsub; s++) {
            float p = p0;
            int code = myidx_tok;
            for (int j = 0; j < m; j++)
                if ((s >> j) & 1) { p *= ev[j]; code ^= bp[j]; }
            atomicAdd(&g_avg_prob[code], p);
        }

        // reduce commit & entropy within the two stat warps
#pragma unroll
        for (int off = 16; off > 0; off >>= 1) {
            cm  += __shfl_down_sync(0xffffffffu, cm,  off);
            ent += __shfl_down_sync(0xffffffffu, ent, off);
        }
        if ((tid & 31) == 0) {
            atomicAdd(&g_ent, (double)ent);
            atomicAdd(&g_commit, (double)cm);
        }
    }

    // ---- completion counter: last block finalizes scalars + resets scratch ----
    __threadfence();
    __syncthreads();
    if (tid == 0) {
        int prev = atomicAdd(&g_ctr, 1);
        s_last = (prev == NBLK - 1);
    }
    __syncthreads();
    if (!s_last) return;

    __threadfence();   // acquire: all blocks' atomics visible
    {
        double cbe = 0.0;
        int cnt = 0;
        for (int i = tid; i < CS; i += NTHR) {
            float ap_raw = __ldcg(&g_avg_prob[i]);
            int   oc     = __ldcg(&g_occ[i]);
            if (ap_raw != 0.0f || oc != 0) {
                float ap = ap_raw * (1.0f / NTOK);
                cbe += (double)(-ap * logf(fmaxf(ap, 1e-20f)));
                cnt += oc;
                g_avg_prob[i] = 0.0f;
                g_occ[i] = 0;
            }
        }
#pragma unroll
        for (int off = 16; off > 0; off >>= 1) {
            cbe += __shfl_down_sync(0xffffffffu, cbe, off);
            cnt += __shfl_down_sync(0xffffffffu, cnt, off);
        }
        if ((tid & 31) == 0) { s_red[tid >> 5] = cbe; s_redc[tid >> 5] = cnt; }
        __syncthreads();
        if (tid == 0) {
            double tcbe = 0.0; int tcnt = 0;
#pragma unroll
            for (int w = 0; w < 16; w++) { tcbe += s_red[w]; tcnt += s_redc[w]; }
            double ge = *((volatile double*)&g_ent);
            double gc = *((volatile double*)&g_commit);
            double pse = ge / (double)NTOK;
            double commit = gc / (double)(NTOK * CD);
            double aux = 0.1 * (pse - tcbe) + 0.25 * commit;
            out[out_size - 2] = (float)aux;
            out[out_size - 1] = (float)tcnt / (float)CS;
            // reset scalars for the next graph replay
            g_ent = 0.0;
            g_commit = 0.0;
            g_ctr = 0;
        }
    }
}

// ---------------- launch ----------------
extern "C" void kernel_launch(void* const* d_in, const int* in_sizes, int n_in,
                              void* d_out, int out_size) {
    const float* z_e   = (const float*)d_in[0];
    const float* W_in  = (const float*)d_in[1];
    const float* b_in  = (const float*)d_in[2];
    const float* W_out = (const float*)d_in[3];
    const float* b_out = (const float*)d_in[4];
    float* out = (float*)d_out;

    k_fused<<<NBLK, NTHR>>>(z_e, W_in, b_in, W_out, b_out, out, out_size);
}

// round 5
// speedup vs baseline: 1.7698x; 1.7698x over previous
#include <cuda_runtime.h>
#include <math.h>

#define T_LEN 4096
#define NB 2
#define DIM 512
#define CD 14
#define CS 16384
#define NTOK (NB * T_LEN)   // 8192

// ---------------- scratch (zero-initialized at module load; k_out's reduction
// blocks reset everything they consume, so graph replays start clean) --------
__device__ float  g_avg_prob[CS];
__device__ int    g_occ[CS];
__device__ int    g_idx[NTOK];
__device__ double g_ent;
__device__ double g_commit;
__device__ double g_cbe;
__device__ int    g_occn;
__device__ int    g_ctr;

// ---------------- K1: fused in-projection + per-token stats ----------------
// Grid: 256 blocks x 512 threads. Each block: 32 tokens, 16 c-groups of 32 channels.
#define TPB 32
#define CG  16
#define CPT (DIM / CG)       // 32
#define NTHR (TPB * CG)      // 512

__global__ __launch_bounds__(NTHR) void k_main(
    const float* __restrict__ z_e,   // (B, DIM, T)
    const float* __restrict__ W_in,  // (CD, DIM)
    const float* __restrict__ b_in)  // (CD,)
{
    // One 32KB buffer, time-multiplexed:
    //   phase A: Ws   = buf[0 .. 8192)          W_in transposed+padded [c*16 + d]
    //   phase B: part = buf[0 .. CG*TPB*CD)     per c-group partials (7168 floats)
    //            xs   = buf[7232 .. 7232+448)   reduced x per token
    __shared__ float buf[DIM * 16];
    float* Ws   = buf;
    float* part = buf;
    float* xs   = buf + 7232;

    const int tid = threadIdx.x;

    for (int i = tid; i < DIM * 16; i += NTHR) {
        int c = i >> 4, d = i & 15;
        Ws[i] = (d < CD) ? W_in[d * DIM + c] : 0.0f;
    }
    __syncthreads();

    const int u = tid & 31;          // token lane
    const int g = tid >> 5;          // c-group
    const int tok0 = blockIdx.x * TPB;
    const int b = tok0 >> 12;
    const int tbase = tok0 & (T_LEN - 1);
    const float* zp = z_e + (size_t)b * DIM * T_LEN + tbase + u;

    float acc[CD];
#pragma unroll
    for (int d = 0; d < CD; d++) acc[d] = 0.0f;

    const int c0 = g * CPT;
#pragma unroll 4
    for (int cc = 0; cc < CPT; cc++) {
        int c = c0 + cc;
        float z = __ldg(zp + (size_t)c * T_LEN);
        const float4* w4 = reinterpret_cast<const float4*>(&Ws[c << 4]);
        float4 wa = w4[0], wb = w4[1], wc = w4[2], wd = w4[3];
        acc[0]  += z * wa.x;  acc[1]  += z * wa.y;  acc[2]  += z * wa.z;  acc[3]  += z * wa.w;
        acc[4]  += z * wb.x;  acc[5]  += z * wb.y;  acc[6]  += z * wb.z;  acc[7]  += z * wb.w;
        acc[8]  += z * wc.x;  acc[9]  += z * wc.y;  acc[10] += z * wc.z;  acc[11] += z * wc.w;
        acc[12] += z * wd.x;  acc[13] += z * wd.y;
    }
    __syncthreads();   // Ws dead; buffer reused as part/xs

    {
        float* pr = &part[(g * TPB + u) * CD];
#pragma unroll
        for (int d = 0; d < CD; d++) pr[d] = acc[d];
    }
    __syncthreads();

    for (int i = tid; i < TPB * CD; i += NTHR) {
        float s = 0.0f;
#pragma unroll
        for (int gg = 0; gg < CG; gg++) s += part[gg * TPB * CD + i];
        xs[i] = s + __ldg(&b_in[i % CD]);
    }
    __syncthreads();

    // warp 0: per-token stats (token = tok0 + tid)
    if (tid < TPB) {
        const int tok = tok0 + tid;
        float x[CD];
#pragma unroll
        for (int d = 0; d < CD; d++) x[d] = xs[tid * CD + d];

        int idx = 0;
#pragma unroll
        for (int d = 0; d < CD; d++)
            if (x[d] > 0.0f) idx |= (1 << (13 - d));
        g_idx[tok] = idx;
        g_occ[idx] = 1;

        float cm = 0.0f;
#pragma unroll
        for (int d = 0; d < CD; d++) {
            float s = (x[d] > 0.0f) ? 1.0f : -1.0f;
            float df = x[d] - s;
            cm += df * df;
        }

        float ent = 0.0f;
        float p0 = 1.0f;
        float ev[CD];
        int bp[CD];
        int m = 0;
#pragma unroll
        for (int d = 0; d < CD; d++) {
            float t = 400.0f * fabsf(x[d]);
            float e = expf(-t);                      // q/(1-q), never overflows
            p0 *= 1.0f / (1.0f + e);
            ent += log1pf(e) + t * e / (1.0f + e);   // stable Bernoulli entropy
            if (e >= 1e-8f) { ev[m] = e; bp[m] = 1 << (13 - d); m++; }
        }

        const int nsub = 1 << m;
        for (int s = 0; s < nsub; s++) {
            float p = p0;
            int code = idx;
            for (int j = 0; j < m; j++)
                if ((s >> j) & 1) { p *= ev[j]; code ^= bp[j]; }
            atomicAdd(&g_avg_prob[code], p);
        }

#pragma unroll
        for (int off = 16; off > 0; off >>= 1) {
            cm  += __shfl_down_sync(0xffffffffu, cm,  off);
            ent += __shfl_down_sync(0xffffffffu, ent, off);
        }
        if (tid == 0) {
            atomicAdd(&g_ent, (double)ent);
            atomicAdd(&g_commit, (double)cm);
        }
    }
}

// ---------------- K2: z_q writeout + codebook reduction + scalar finalize ----
// Blocks 0..63 also reduce 256 codebook bins each (resetting them for the next
// replay); the last of those 64 blocks combines everything and writes the
// aux-loss & usage scalars, then resets the scalar accumulators.
__global__ __launch_bounds__(256) void k_out(
    const float* __restrict__ W_out,  // (DIM, CD)
    const float* __restrict__ b_out,  // (DIM,)
    float* __restrict__ out, int out_size)
{
    __shared__ double sh[256];
    __shared__ int    shc[256];
    __shared__ int    s_last;

    const int tid = threadIdx.x;
    const int e = blockIdx.x * 256 + tid;           // [0, 1048576)
    const int tq = e & 1023;
    const int c  = (e >> 10) & 511;
    const int b  = e >> 19;
    const int t  = tq << 2;

    const int4 iv = *reinterpret_cast<const int4*>(&g_idx[b * T_LEN + t]);
    int id[4] = { iv.x, iv.y, iv.z, iv.w };

    int wi[CD];
#pragma unroll
    for (int d = 0; d < CD; d++) wi[d] = __float_as_int(__ldg(&W_out[c * CD + d]));
    const float bc = __ldg(&b_out[c]);

    float r[4];
#pragma unroll
    for (int j = 0; j < 4; j++) {
        const unsigned nix = ~(unsigned)id[j];
        float s = bc;
#pragma unroll
        for (int d = 0; d < CD; d++) {
            unsigned sgn = (nix << (18 + d)) & 0x80000000u;
            s += __int_as_float((unsigned)wi[d] ^ sgn);
        }
        r[j] = s;
    }

    float4* op = reinterpret_cast<float4*>(&out[((size_t)(b * DIM + c)) * T_LEN + t]);
    *op = make_float4(r[0], r[1], r[2], r[3]);

    // ---- codebook entropy + occupancy: 64 blocks x 256 threads cover CS ----
    if (blockIdx.x < 64) {
        const int i = blockIdx.x * 256 + tid;
        float ap_raw = g_avg_prob[i];
        int   oc     = g_occ[i];
        double v = 0.0;
        if (ap_raw != 0.0f || oc != 0) {
            float ap = ap_raw * (1.0f / NTOK);
            v = (double)(-ap * logf(fmaxf(ap, 1e-20f)));
            g_avg_prob[i] = 0.0f;   // reset for next graph replay
            g_occ[i] = 0;
        }
        sh[tid] = v; shc[tid] = oc;
        __syncthreads();
        for (int s = 128; s > 0; s >>= 1) {
            if (tid < s) { sh[tid] += sh[tid + s]; shc[tid] += shc[tid + s]; }
            __syncthreads();
        }
        if (tid == 0) {
            atomicAdd(&g_cbe, sh[0]);
            atomicAdd(&g_occn, shc[0]);
            __threadfence();
            int prev = atomicAdd(&g_ctr, 1);
            s_last = (prev == 63);
        }
        __syncthreads();
        if (s_last && tid == 0) {
            __threadfence();   // acquire: all 64 blocks' partials visible
            double cbe = *((volatile double*)&g_cbe);
            int    occ = *((volatile int*)&g_occn);
            double ge  = *((volatile double*)&g_ent);
            double gc  = *((volatile double*)&g_commit);
            double pse = ge / (double)NTOK;
            double commit = gc / (double)(NTOK * CD);
            double aux = 0.1 * (pse - cbe) + 0.25 * commit;
            out[out_size - 2] = (float)aux;
            out[out_size - 1] = (float)occ / (float)CS;
            // reset scalar accumulators for the next replay
            g_cbe = 0.0; g_occn = 0;
            g_ent = 0.0; g_commit = 0.0;
            g_ctr = 0;
        }
    }
}

// ---------------- launch ----------------
extern "C" void kernel_launch(void* const* d_in, const int* in_sizes, int n_in,
                              void* d_out, int out_size) {
    const float* z_e   = (const float*)d_in[0];
    const float* W_in  = (const float*)d_in[1];
    const float* b_in  = (const float*)d_in[2];
    const float* W_out = (const float*)d_in[3];
    const float* b_out = (const float*)d_in[4];
    float* out = (float*)d_out;

    k_main<<<NTOK / TPB, NTHR>>>(z_e, W_in, b_in);
    k_out<<<(NB * DIM * T_LEN / 4) / 256, 256>>>(W_out, b_out, out, out_size);
}

// round 6
// speedup vs baseline: 1.8876x; 1.0666x over previous
#include <cuda_runtime.h>
#include <math.h>

#define T_LEN 4096
#define NB 2
#define DIM 512
#define CD 14
#define CS 16384
#define NTOK (NB * T_LEN)   // 8192

// ---------------- scratch (zero-initialized at module load; k_out's reduction
// blocks reset everything they consume, so graph replays start clean) --------
__device__ float  g_avg_prob[CS];
__device__ int    g_occ[CS];
__device__ int    g_idx[NTOK];
__device__ double g_ent;
__device__ double g_commit;
__device__ double g_cbe;
__device__ int    g_occn;
__device__ int    g_ctr;

// ---------------- K1: fused in-projection + per-token stats ----------------
// Grid: 256 blocks x 512 threads. Each block: 32 tokens, 16 c-groups of 32 channels.
#define TPB 32
#define CG  16
#define CPT (DIM / CG)       // 32
#define NTHR (TPB * CG)      // 512

__global__ __launch_bounds__(NTHR) void k_main(
    const float* __restrict__ z_e,   // (B, DIM, T)
    const float* __restrict__ W_in,  // (CD, DIM)
    const float* __restrict__ b_in)  // (CD,)
{
    __shared__ float buf[DIM * 16];
    float* Ws   = buf;
    float* part = buf;
    float* xs   = buf + 7232;

    const int tid = threadIdx.x;

    for (int i = tid; i < DIM * 16; i += NTHR) {
        int c = i >> 4, d = i & 15;
        Ws[i] = (d < CD) ? W_in[d * DIM + c] : 0.0f;
    }
    __syncthreads();

    const int u = tid & 31;          // token lane
    const int g = tid >> 5;          // c-group
    const int tok0 = blockIdx.x * TPB;
    const int b = tok0 >> 12;
    const int tbase = tok0 & (T_LEN - 1);
    const float* zp = z_e + (size_t)b * DIM * T_LEN + tbase + u;

    float acc[CD];
#pragma unroll
    for (int d = 0; d < CD; d++) acc[d] = 0.0f;

    const int c0 = g * CPT;
#pragma unroll 4
    for (int cc = 0; cc < CPT; cc++) {
        int c = c0 + cc;
        float z = __ldg(zp + (size_t)c * T_LEN);
        const float4* w4 = reinterpret_cast<const float4*>(&Ws[c << 4]);
        float4 wa = w4[0], wb = w4[1], wc = w4[2], wd = w4[3];
        acc[0]  += z * wa.x;  acc[1]  += z * wa.y;  acc[2]  += z * wa.z;  acc[3]  += z * wa.w;
        acc[4]  += z * wb.x;  acc[5]  += z * wb.y;  acc[6]  += z * wb.z;  acc[7]  += z * wb.w;
        acc[8]  += z * wc.x;  acc[9]  += z * wc.y;  acc[10] += z * wc.z;  acc[11] += z * wc.w;
        acc[12] += z * wd.x;  acc[13] += z * wd.y;
    }
    __syncthreads();   // Ws dead; buffer reused as part/xs

    {
        float* pr = &part[(g * TPB + u) * CD];
#pragma unroll
        for (int d = 0; d < CD; d++) pr[d] = acc[d];
    }
    __syncthreads();

    for (int i = tid; i < TPB * CD; i += NTHR) {
        float s = 0.0f;
#pragma unroll
        for (int gg = 0; gg < CG; gg++) s += part[gg * TPB * CD + i];
        xs[i] = s + __ldg(&b_in[i % CD]);
    }
    __syncthreads();

    // warp 0: per-token stats (token = tok0 + tid)
    if (tid < TPB) {
        const int tok = tok0 + tid;
        float x[CD];
#pragma unroll
        for (int d = 0; d < CD; d++) x[d] = xs[tid * CD + d];

        int idx = 0;
#pragma unroll
        for (int d = 0; d < CD; d++)
            if (x[d] > 0.0f) idx |= (1 << (13 - d));
        g_idx[tok] = idx;
        g_occ[idx] = 1;

        float cm = 0.0f;
#pragma unroll
        for (int d = 0; d < CD; d++) {
            float s = (x[d] > 0.0f) ? 1.0f : -1.0f;
            float df = x[d] - s;
            cm += df * df;
        }

        float ent = 0.0f;
        float p0 = 1.0f;
        float ev[CD];
        int bp[CD];
        int m = 0;
#pragma unroll
        for (int d = 0; d < CD; d++) {
            float t = 400.0f * fabsf(x[d]);
            float e = expf(-t);                      // q/(1-q), never overflows
            p0 *= 1.0f / (1.0f + e);
            ent += log1pf(e) + t * e / (1.0f + e);   // stable Bernoulli entropy
            if (e >= 1e-8f) { ev[m] = e; bp[m] = 1 << (13 - d); m++; }
        }

        const int nsub = 1 << m;
        for (int s = 0; s < nsub; s++) {
            float p = p0;
            int code = idx;
            for (int j = 0; j < m; j++)
                if ((s >> j) & 1) { p *= ev[j]; code ^= bp[j]; }
            atomicAdd(&g_avg_prob[code], p);
        }

#pragma unroll
        for (int off = 16; off > 0; off >>= 1) {
            cm  += __shfl_down_sync(0xffffffffu, cm,  off);
            ent += __shfl_down_sync(0xffffffffu, ent, off);
        }
        if (tid == 0) {
            atomicAdd(&g_ent, (double)ent);
            atomicAdd(&g_commit, (double)cm);
        }
    }
}

// ---------------- K2: z_q writeout via split-bit lookup tables ---------------
// Per block: one channel c, 1024 tokens. Two 128-entry smem tables:
//   lo[m] = sum_{d=7..13} (bit(13-d) of m ? +1 : -1) * W_out[c,d]
//   hi[h] = sum_{d=0..6}  (bit(6-d)  of h ? +1 : -1) * W_out[c,d]
// out = b_out[c] + lo[idx & 127] + hi[idx >> 7]   (2 LDS + 2 FADD per element)
// Blocks 0..63 also reduce the 16384 codebook bins; the last block finalizes
// the scalars and resets all scratch for the next graph replay.
__global__ __launch_bounds__(256) void k_out(
    const float* __restrict__ W_out,  // (DIM, CD)
    const float* __restrict__ b_out,  // (DIM,)
    float* __restrict__ out, int out_size)
{
    __shared__ float tabs[256];       // [0..127]=lo, [128..255]=hi
    __shared__ double sh[256];
    __shared__ int    shc[256];
    __shared__ int    s_last;

    const int tid = threadIdx.x;
    const int bid = blockIdx.x;       // 4096 blocks = b(1) x q(2) x c(9) bits
    const int c = bid & 511;
    const int q = (bid >> 9) & 3;
    const int b = bid >> 11;
    const int t0 = q << 10;           // 1024-token chunk

    // build tables: one entry per thread, 7 signed adds each
    {
        float w[7];
        const int base = (tid < 128) ? 7 : 0;      // lo: d=7..13, hi: d=0..6
        const int m = tid & 127;
#pragma unroll
        for (int d = 0; d < 7; d++) w[d] = __ldg(&W_out[c * CD + base + d]);
        float s = 0.0f;
#pragma unroll
        for (int d = 0; d < 7; d++) {
            // for entry m, dim (base+d) corresponds to bit (6-d) of m
            unsigned sgn = (((unsigned)m >> (6 - d)) & 1u) ? 0u : 0x80000000u;
            s += __int_as_float(__float_as_int(w[d]) ^ sgn);
        }
        tabs[tid] = s;
    }
    const float bc = __ldg(&b_out[c]);
    __syncthreads();

    // 4 tokens per thread
    const int t = t0 + (tid << 2);
    const int4 iv = *reinterpret_cast<const int4*>(&g_idx[b * T_LEN + t]);
    int id[4] = { iv.x, iv.y, iv.z, iv.w };

    float r[4];
#pragma unroll
    for (int j = 0; j < 4; j++)
        r[j] = bc + tabs[id[j] & 127] + tabs[128 + (id[j] >> 7)];

    float4* op = reinterpret_cast<float4*>(&out[((size_t)(b * DIM + c)) * T_LEN + t]);
    *op = make_float4(r[0], r[1], r[2], r[3]);

    // ---- codebook entropy + occupancy: 64 blocks x 256 threads cover CS ----
    if (bid < 64) {
        const int i = bid * 256 + tid;
        float ap_raw = g_avg_prob[i];
        int   oc     = g_occ[i];
        double v = 0.0;
        if (ap_raw != 0.0f || oc != 0) {
            float ap = ap_raw * (1.0f / NTOK);
            v = (double)(-ap * logf(fmaxf(ap, 1e-20f)));
            g_avg_prob[i] = 0.0f;   // reset for next graph replay
            g_occ[i] = 0;
        }
        sh[tid] = v; shc[tid] = oc;
        __syncthreads();
        for (int s = 128; s > 0; s >>= 1) {
            if (tid < s) { sh[tid] += sh[tid + s]; shc[tid] += shc[tid + s]; }
            __syncthreads();
        }
        if (tid == 0) {
            atomicAdd(&g_cbe, sh[0]);
            atomicAdd(&g_occn, shc[0]);
            __threadfence();
            int prev = atomicAdd(&g_ctr, 1);
            s_last = (prev == 63);
        }
        __syncthreads();
        if (s_last && tid == 0) {
            __threadfence();   // acquire: all 64 blocks' partials visible
            double cbe = *((volatile double*)&g_cbe);
            int    occ = *((volatile int*)&g_occn);
            double ge  = *((volatile double*)&g_ent);
            double gc  = *((volatile double*)&g_commit);
            double pse = ge / (double)NTOK;
            double commit = gc / (double)(NTOK * CD);
            double aux = 0.1 * (pse - cbe) + 0.25 * commit;
            out[out_size - 2] = (float)aux;
            out[out_size - 1] = (float)occ / (float)CS;
            g_cbe = 0.0; g_occn = 0;
            g_ent = 0.0; g_commit = 0.0;
            g_ctr = 0;
        }
    }
}

// ---------------- launch ----------------
extern "C" void kernel_launch(void* const* d_in, const int* in_sizes, int n_in,
                              void* d_out, int out_size) {
    const float* z_e   = (const float*)d_in[0];
    const float* W_in  = (const float*)d_in[1];
    const float* b_in  = (const float*)d_in[2];
    const float* W_out = (const float*)d_in[3];
    const float* b_out = (const float*)d_in[4];
    float* out = (float*)d_out;

    k_main<<<NTOK / TPB, NTHR>>>(z_e, W_in, b_in);
    k_out<<<4096, 256>>>(W_out, b_out, out, out_size);
}